// round 11
// baseline (speedup 1.0000x reference)
#include <cuda_runtime.h>
#include <cstddef>
#include <cstdint>

#define B_ 512
#define T_ 1024
#define U_ 128
#define RSTR 160   // h row stride in floats: 128B-aligned rows, conflict-benign

typedef unsigned long long ull;
typedef unsigned int uint;

// Allocation-free scratch: two 256MB staging buffers as device globals (.bss).
__device__ float g_pbuf[(size_t)T_ * B_ * U_];  // px1
__device__ float g_p2[(size_t)T_ * B_ * U_];    // p2 (written by fused recurBC)

// ---------- packed f32x2 helpers (Blackwell, PTX-only) ----------
__device__ __forceinline__ ull bc2(float v) {
    ull r; asm("mov.b64 %0, {%1,%1};" : "=l"(r) : "f"(v)); return r;
}
__device__ __forceinline__ ull pack2(float a, float b) {
    ull r; asm("mov.b64 %0, {%1,%2};" : "=l"(r) : "f"(a), "f"(b)); return r;
}
__device__ __forceinline__ void fma2(ull& d, ull a, ull b) {
    asm("fma.rn.f32x2 %0, %1, %2, %0;" : "+l"(d) : "l"(a), "l"(b));
}
__device__ __forceinline__ ull add2(ull a, ull b) {
    ull r; asm("add.rn.f32x2 %0, %1, %2;" : "=l"(r) : "l"(a), "l"(b)); return r;
}
__device__ __forceinline__ void unpk(ull v, float& lo, float& hi) {
    asm("mov.b64 {%0,%1}, %2;" : "=f"(lo), "=f"(hi) : "l"(v));
}

// h layout: the four sub-slices' simultaneous 16B chunks are adjacent within
// 64B -> every broadcast LDS.128 is one wavefront.
//   k = sub*32 + i*4 + m  ->  phys = i*16 + sub*4 + m   (i=0..7)
__device__ __forceinline__ int hphys(int k) {
    return ((k >> 2) & 7) * 16 + (k >> 5) * 4 + (k & 3);
}

// ============================================================================
// Parallel GEMM + bias (unchanged — known-good since R4)
// ============================================================================
template <int KD, bool XLAY>
__global__ __launch_bounds__(256, 2)
void gemm_bias(const float* __restrict__ A, const float* __restrict__ W,
               const float* __restrict__ bias, float* __restrict__ out)
{
    extern __shared__ float sm[];
    float* Ws = sm;               // [KD][128]
    float* As = sm + KD * U_;     // [KD][68]
    const int tid  = threadIdx.x;
    const int row0 = blockIdx.x * 64;

    for (int i = tid; i < KD * U_; i += 256) Ws[i] = W[i];

    for (int i = tid; i < 64 * KD; i += 256) {
        int r = i / KD, k = i - r * KD;
        size_t off;
        if (XLAY) {
            int t = row0 >> 9;
            int b = (row0 & (B_ - 1)) + r;
            off = ((size_t)b * T_ + t) * KD + k;
        } else {
            off = (size_t)(row0 + r) * KD + k;
        }
        As[k * 68 + r] = A[off];
    }
    __syncthreads();

    const int u0 = (tid & 31) * 4;
    const int rb = (tid >> 5) * 8;

    ull acc[4][4];
#pragma unroll
    for (int a = 0; a < 4; a++)
#pragma unroll
        for (int b = 0; b < 4; b++) acc[a][b] = 0ULL;

#pragma unroll 4
    for (int k = 0; k < KD; k++) {
        ulonglong2 a01 = *(const ulonglong2*)(As + k * 68 + rb);
        ulonglong2 a23 = *(const ulonglong2*)(As + k * 68 + rb + 4);
        float4 w4 = *(const float4*)(Ws + k * U_ + u0);
        ull w;
        w = bc2(w4.x);
        fma2(acc[0][0], a01.x, w); fma2(acc[0][1], a01.y, w);
        fma2(acc[0][2], a23.x, w); fma2(acc[0][3], a23.y, w);
        w = bc2(w4.y);
        fma2(acc[1][0], a01.x, w); fma2(acc[1][1], a01.y, w);
        fma2(acc[1][2], a23.x, w); fma2(acc[1][3], a23.y, w);
        w = bc2(w4.z);
        fma2(acc[2][0], a01.x, w); fma2(acc[2][1], a01.y, w);
        fma2(acc[2][2], a23.x, w); fma2(acc[2][3], a23.y, w);
        w = bc2(w4.w);
        fma2(acc[3][0], a01.x, w); fma2(acc[3][1], a01.y, w);
        fma2(acc[3][2], a23.x, w); fma2(acc[3][3], a23.y, w);
    }

    float f[4][8];
#pragma unroll
    for (int uu = 0; uu < 4; uu++)
#pragma unroll
        for (int rp = 0; rp < 4; rp++) unpk(acc[uu][rp], f[uu][2 * rp], f[uu][2 * rp + 1]);

    float4 bv = *(const float4*)(bias + u0);
#pragma unroll
    for (int rr = 0; rr < 8; rr++) {
        float4 o = make_float4(f[0][rr] + bv.x, f[1][rr] + bv.y,
                               f[2][rr] + bv.z, f[3][rr] + bv.w);
        *(float4*)(out + (size_t)(row0 + rb + rr) * U_ + u0) = o;
    }
}

// ============================================================================
// Recurrence v4: 512 threads = 128 units x 4 k-slices -> 4 warps/SMSP
// (2x latency hiding at identical SMSP totals vs v2). Per thread per step:
// 32 LDS.128 (1 wf each) + 64 FFMA2 (D) / 128 FFMA2 (BC, fused p2 GEMM).
// 2-round select-fold butterfly over the 4 sub lanes leaves lane sub owning
// row sub -> ALL threads share the epilogue (1 LDG + 1 STS (+1 STG) each).
// FUSE=true : phase B+C (h1 recurrence + p2 = h1@Wx2 + b2, lagged one step).
// FUSE=false: phase D (+ final dout = h2_T . Wd + bd).
// ============================================================================
template <bool FUSE>
__global__ __launch_bounds__(512, 1)
void recur4(const float* __restrict__ p, const float* __restrict__ Wr,
            const float* __restrict__ Wq, const float* __restrict__ bq,
            float* __restrict__ qout,
            const float* __restrict__ Wd, const float* __restrict__ bd,
            float* __restrict__ dout)
{
    __shared__ __align__(16) float hs[2][4 * RSTR];
    __shared__ float part_s[4][U_];

    const int tid = threadIdx.x;
    const int u   = tid >> 2;          // unit 0..127
    const int sub = tid & 3;           // k-slice 0..3 (adjacent lanes)
    const int r0  = blockIdx.x * 4;

    // 16 packed k-pair weights per matrix for k = sub*32 .. sub*32+31
    ull wp[16], wq[16];
#pragma unroll
    for (int j = 0; j < 16; j++) {
        int k = sub * 32 + 2 * j;
        wp[j] = pack2(Wr[(size_t)k * U_ + u], Wr[(size_t)(k + 1) * U_ + u]);
        if (FUSE)
            wq[j] = pack2(Wq[(size_t)k * U_ + u], Wq[(size_t)(k + 1) * U_ + u]);
    }
    const float bqv = FUSE ? bq[u] : 0.f;

    for (int i = tid; i < 4 * RSTR; i += 512) hs[0][i] = 0.f;

    const int physu = hphys(u);
    // owned (row, unit) stream of p
    const float* pown = p + ((size_t)(r0 + sub)) * U_ + u;
    float pv = pown[0];
    float s = 0.f;
    __syncthreads();

    const int TEND = FUSE ? T_ + 1 : T_;
    for (int t = 0; t < TEND; t++) {
        int tn = (t < T_ - 1) ? t + 1 : T_ - 1;
        float pnext = pown[(size_t)tn * B_ * U_];

        const float* hb = hs[t & 1];
        float*       hn = hs[(t + 1) & 1];

        ull acc[4] = {0ULL, 0ULL, 0ULL, 0ULL};
        ull bcc[4] = {0ULL, 0ULL, 0ULL, 0ULL};
#pragma unroll
        for (int r = 0; r < 4; r++) {
            const float* rb = hb + r * RSTR + sub * 4;
#pragma unroll
            for (int i = 0; i < 8; i++) {
                ulonglong2 hv = *(const ulonglong2*)(rb + i * 16);
                fma2(acc[r], hv.x, wp[2 * i]);
                fma2(acc[r], hv.y, wp[2 * i + 1]);
                if (FUSE) {
                    fma2(bcc[r], hv.x, wq[2 * i]);
                    fma2(bcc[r], hv.y, wq[2 * i + 1]);
                }
            }
        }

        // ---- fold over 4 sub lanes; lane ends owning row = sub ----
        const bool g2 = (sub & 2) != 0;
        ull sa0 = g2 ? acc[0] : acc[2];
        ull sa1 = g2 ? acc[1] : acc[3];
        sa0 = __shfl_xor_sync(0xffffffffu, sa0, 2);
        sa1 = __shfl_xor_sync(0xffffffffu, sa1, 2);
        ull A0 = add2(g2 ? acc[2] : acc[0], sa0);   // row (sub&2)
        ull A1 = add2(g2 ? acc[3] : acc[1], sa1);   // row (sub&2)+1

        ull B0 = 0ULL, B1 = 0ULL;
        if (FUSE) {
            ull sb0 = g2 ? bcc[0] : bcc[2];
            ull sb1 = g2 ? bcc[1] : bcc[3];
            sb0 = __shfl_xor_sync(0xffffffffu, sb0, 2);
            sb1 = __shfl_xor_sync(0xffffffffu, sb1, 2);
            B0 = add2(g2 ? bcc[2] : bcc[0], sb0);
            B1 = add2(g2 ? bcc[3] : bcc[1], sb1);
        }

        const bool g1 = (sub & 1) != 0;
        ull sA = g1 ? A0 : A1;
        sA = __shfl_xor_sync(0xffffffffu, sA, 1);
        ull FA = add2(g1 ? A1 : A0, sA);            // row sub, packed k-parity
        float alo, ahi; unpk(FA, alo, ahi);
        float hsum = alo + ahi;

        if (FUSE) {
            ull sB = g1 ? B0 : B1;
            sB = __shfl_xor_sync(0xffffffffu, sB, 1);
            ull FB = add2(g1 ? B1 : B0, sB);
            float blo, bhi; unpk(FB, blo, bhi);
            if (t > 0)
                qout[((size_t)(t - 1) * B_ + r0 + sub) * U_ + u] = blo + bhi + bqv;
        }

        if (!FUSE || t < T_) {
            s = fmaxf(hsum + pv, 0.f);
            hn[sub * RSTR + physu] = s;
            pv = pnext;
        }
        __syncthreads();
    }

    if (!FUSE) {
        // each thread owns final h(row sub, unit u) in s
        part_s[sub][u] = s * Wd[u];
        __syncthreads();
        const int wid = tid >> 5, lid = tid & 31;
        if (wid < 4) {
            const float* pr = part_s[wid];
            float a = pr[lid] + pr[lid + 32] + pr[lid + 64] + pr[lid + 96];
#pragma unroll
            for (int m = 16; m > 0; m >>= 1)
                a += __shfl_xor_sync(0xffffffffu, a, m);
            if (lid == 0) dout[r0 + wid] = a + bd[0];
        }
    }
}

// ============================================================================
extern "C" void kernel_launch(void* const* d_in, const int* in_sizes, int n_in,
                              void* d_out, int out_size)
{
    (void)in_sizes; (void)n_in; (void)out_size;
    const float* x   = (const float*)d_in[0];
    const float* Wx1 = (const float*)d_in[1];
    const float* Wh1 = (const float*)d_in[2];
    const float* b1  = (const float*)d_in[3];
    const float* Wx2 = (const float*)d_in[4];
    const float* Wh2 = (const float*)d_in[5];
    const float* b2  = (const float*)d_in[6];
    const float* Wd  = (const float*)d_in[7];
    const float* bd  = (const float*)d_in[8];
    float* out = (float*)d_out;

    float *pbuf, *p2buf;
    cudaGetSymbolAddress((void**)&pbuf, g_pbuf);
    cudaGetSymbolAddress((void**)&p2buf, g_p2);

    const int ngrid = (T_ * B_) / 64;                        // 8192 tiles
    const int smemA = (64 * U_ + 64 * 68) * sizeof(float);   // 50176 B
    cudaFuncSetAttribute(gemm_bias<64, true>,
                         cudaFuncAttributeMaxDynamicSharedMemorySize, smemA);

    // Phase A: px1 = x @ Wx1 + b1           (layout [t][b][u])
    gemm_bias<64, true><<<ngrid, 256, smemA>>>(x, Wx1, b1, pbuf);
    // Phase B+C fused: h1 recurrence + p2 = h1 @ Wx2 + b2
    recur4<true><<<B_ / 4, 512>>>(pbuf, Wh1, Wx2, b2, p2buf,
                                  nullptr, nullptr, nullptr);
    // Phase D: h2 recurrence + final projection
    recur4<false><<<B_ / 4, 512>>>(p2buf, Wh2, nullptr, nullptr, nullptr,
                                   Wd, bd, out);
}

// round 12
// speedup vs baseline: 1.4802x; 1.4802x over previous
#include <cuda_runtime.h>
#include <cstddef>
#include <cstdint>

#define B_ 512
#define T_ 1024
#define U_ 128
#define RSTR 136   // padded h row stride in floats (128 data + 8 pad)

typedef unsigned long long ull;
typedef unsigned int uint;

// Allocation-free scratch (device global, .bss)
__device__ float g_pbuf[(size_t)T_ * B_ * U_];  // px1

// ---------- packed f32x2 helpers (Blackwell, PTX-only) ----------
__device__ __forceinline__ ull bc2(float v) {
    ull r; asm("mov.b64 %0, {%1,%1};" : "=l"(r) : "f"(v)); return r;
}
__device__ __forceinline__ ull pack2(float a, float b) {
    ull r; asm("mov.b64 %0, {%1,%2};" : "=l"(r) : "f"(a), "f"(b)); return r;
}
__device__ __forceinline__ void fma2(ull& d, ull a, ull b) {
    asm("fma.rn.f32x2 %0, %1, %2, %0;" : "+l"(d) : "l"(a), "l"(b));
}
__device__ __forceinline__ void unpk(ull v, float& lo, float& hi) {
    asm("mov.b64 {%0,%1}, %2;" : "=f"(lo), "=f"(hi) : "l"(v));
}

// h layout: the two ks slices' simultaneous 16B chunks are adjacent -> every
// broadcast LDS.128 is one wavefront.
//   k = ks*64 + half*32 + i*4 + m  ->  phys = half*64 + i*8 + ks*4 + m
__device__ __forceinline__ int hphys(int k) {
    return ((k >> 5) & 1) * 64 + ((k >> 2) & 7) * 8 + (k >> 6) * 4 + (k & 3);
}

// ============================================================================
// Parallel GEMM + bias (unchanged — known-good since R4)
// ============================================================================
template <int KD, bool XLAY>
__global__ __launch_bounds__(256, 2)
void gemm_bias(const float* __restrict__ A, const float* __restrict__ W,
               const float* __restrict__ bias, float* __restrict__ out)
{
    extern __shared__ float sm[];
    float* Ws = sm;               // [KD][128]
    float* As = sm + KD * U_;     // [KD][68]
    const int tid  = threadIdx.x;
    const int row0 = blockIdx.x * 64;

    for (int i = tid; i < KD * U_; i += 256) Ws[i] = W[i];

    for (int i = tid; i < 64 * KD; i += 256) {
        int r = i / KD, k = i - r * KD;
        size_t off;
        if (XLAY) {
            int t = row0 >> 9;
            int b = (row0 & (B_ - 1)) + r;
            off = ((size_t)b * T_ + t) * KD + k;
        } else {
            off = (size_t)(row0 + r) * KD + k;
        }
        As[k * 68 + r] = A[off];
    }
    __syncthreads();

    const int u0 = (tid & 31) * 4;
    const int rb = (tid >> 5) * 8;

    ull acc[4][4];
#pragma unroll
    for (int a = 0; a < 4; a++)
#pragma unroll
        for (int b = 0; b < 4; b++) acc[a][b] = 0ULL;

#pragma unroll 4
    for (int k = 0; k < KD; k++) {
        ulonglong2 a01 = *(const ulonglong2*)(As + k * 68 + rb);
        ulonglong2 a23 = *(const ulonglong2*)(As + k * 68 + rb + 4);
        float4 w4 = *(const float4*)(Ws + k * U_ + u0);
        ull w;
        w = bc2(w4.x);
        fma2(acc[0][0], a01.x, w); fma2(acc[0][1], a01.y, w);
        fma2(acc[0][2], a23.x, w); fma2(acc[0][3], a23.y, w);
        w = bc2(w4.y);
        fma2(acc[1][0], a01.x, w); fma2(acc[1][1], a01.y, w);
        fma2(acc[1][2], a23.x, w); fma2(acc[1][3], a23.y, w);
        w = bc2(w4.z);
        fma2(acc[2][0], a01.x, w); fma2(acc[2][1], a01.y, w);
        fma2(acc[2][2], a23.x, w); fma2(acc[2][3], a23.y, w);
        w = bc2(w4.w);
        fma2(acc[3][0], a01.x, w); fma2(acc[3][1], a01.y, w);
        fma2(acc[3][2], a23.x, w); fma2(acc[3][3], a23.y, w);
    }

    float f[4][8];
#pragma unroll
    for (int uu = 0; uu < 4; uu++)
#pragma unroll
        for (int rp = 0; rp < 4; rp++) unpk(acc[uu][rp], f[uu][2 * rp], f[uu][2 * rp + 1]);

    float4 bv = *(const float4*)(bias + u0);
#pragma unroll
    for (int rr = 0; rr < 8; rr++) {
        float4 o = make_float4(f[0][rr] + bv.x, f[1][rr] + bv.y,
                               f[2][rr] + bv.z, f[3][rr] + bv.w);
        *(float4*)(out + (size_t)(row0 + rb + rr) * U_ + u0) = o;
    }
}

// ============================================================================
// Fully fused recurrence (B+C+D): proven v2 geometry (256 thr, 2 k-slices,
// 2 warps/SMSP, shfl-pair fold, 1 barrier/step). Per iter t:
//   h1_t    = relu(p1_t + h1_{t-1}@Wh1)                  -> h1s[(t+1)&1]
//   h2_{t-1}= relu(h1_{t-1}@Wx2 + b2 + h2_{t-2}@Wh2)     -> h2s[(t+1)&1]
// Wx2 and Wh2 partials SHARE one accumulator + one fold (linear before relu).
// Loop t=0..T; iter T emits the final h2_{T-1}, then dout = h2.Wd + bd.
// ============================================================================
__global__ __launch_bounds__(256, 1)
void recurBCD(const float* __restrict__ p,
              const float* __restrict__ Wh1c, const float* __restrict__ Wx2c,
              const float* __restrict__ b2c,  const float* __restrict__ Wh2c,
              const float* __restrict__ Wdc,  const float* __restrict__ bdc,
              float* __restrict__ dout)
{
    __shared__ __align__(16) float h1s[2][4 * RSTR];
    __shared__ __align__(16) float h2s[2][4 * RSTR];
    __shared__ float4 part_s[U_];

    const int tid = threadIdx.x;
    const int u   = tid >> 1;
    const int ks  = tid & 1;
    const int r0  = blockIdx.x * 4;
    const bool wr = (ks == 0);

    // 3 x 32 packed k-pair weight columns (loaded once, live all 1025 iters)
    ull wp[32], wq[32], wv[32];
#pragma unroll
    for (int i = 0; i < 32; i++) {
        int k = ks * 64 + 2 * i;
        wp[i] = pack2(Wh1c[(size_t)k * U_ + u], Wh1c[(size_t)(k + 1) * U_ + u]);
        wq[i] = pack2(Wx2c[(size_t)k * U_ + u], Wx2c[(size_t)(k + 1) * U_ + u]);
        wv[i] = pack2(Wh2c[(size_t)k * U_ + u], Wh2c[(size_t)(k + 1) * U_ + u]);
    }
    const float b2v = b2c[u];

    for (int i = tid; i < 4 * RSTR; i += 256) {
        h1s[0][i] = 0.f; h1s[1][i] = 0.f;
        h2s[0][i] = 0.f; h2s[1][i] = 0.f;
    }

    const int physu = hphys(u);
    const float* prow = p + (size_t)r0 * U_ + u;
    float pv[4] = {0.f, 0.f, 0.f, 0.f};
    if (wr) { pv[0] = prow[0]; pv[1] = prow[U_]; pv[2] = prow[2 * U_]; pv[3] = prow[3 * U_]; }
    float hfin[4] = {0.f, 0.f, 0.f, 0.f};
    __syncthreads();

    for (int t = 0; t <= T_; t++) {
        float pn[4] = {0.f, 0.f, 0.f, 0.f};
        if (wr) {
            int tn = (t < T_ - 1) ? t + 1 : T_ - 1;
            const float* pp = prow + (size_t)tn * B_ * U_;
            pn[0] = pp[0]; pn[1] = pp[U_]; pn[2] = pp[2 * U_]; pn[3] = pp[3 * U_];
        }

        const float* hb1 = h1s[t & 1];        // h1_{t-1}
        float*       hn1 = h1s[(t + 1) & 1];
        const float* hb2 = h2s[t & 1];        // h2_{t-2}
        float*       hn2 = h2s[(t + 1) & 1];

        ull acc[4] = {0ULL, 0ULL, 0ULL, 0ULL};   // Wh1 @ h1
        ull bcc[4] = {0ULL, 0ULL, 0ULL, 0ULL};   // Wx2 @ h1 + Wh2 @ h2 (shared)
#pragma unroll
        for (int r = 0; r < 4; r++) {
            const float* rb1 = hb1 + r * RSTR + ks * 4;
            const float* rb2 = hb2 + r * RSTR + ks * 4;
#pragma unroll
            for (int half = 0; half < 2; half++) {
#pragma unroll
                for (int i = 0; i < 8; i++) {
                    int wi = half * 16 + 2 * i;
                    ulonglong2 hv = *(const ulonglong2*)(rb1 + half * 64 + i * 8);
                    fma2(acc[r], hv.x, wp[wi]);
                    fma2(acc[r], hv.y, wp[wi + 1]);
                    fma2(bcc[r], hv.x, wq[wi]);
                    fma2(bcc[r], hv.y, wq[wi + 1]);
                    ulonglong2 gv = *(const ulonglong2*)(rb2 + half * 64 + i * 8);
                    fma2(bcc[r], gv.x, wv[wi]);
                    fma2(bcc[r], gv.y, wv[wi + 1]);
                }
            }
        }

        // cross-slice fold (lane ^ 1), v2-style 32-bit shuffles, no SELs
        float s1[4], s2[4];
#pragma unroll
        for (int r = 0; r < 4; r++) {
            uint lo = (uint)acc[r], hi = (uint)(acc[r] >> 32);
            uint plo = __shfl_xor_sync(0xffffffffu, lo, 1);
            uint phi = __shfl_xor_sync(0xffffffffu, hi, 1);
            s1[r] = __uint_as_float(lo) + __uint_as_float(plo)
                  + __uint_as_float(hi) + __uint_as_float(phi);

            uint blo = (uint)bcc[r], bhi = (uint)(bcc[r] >> 32);
            uint pblo = __shfl_xor_sync(0xffffffffu, blo, 1);
            uint pbhi = __shfl_xor_sync(0xffffffffu, bhi, 1);
            s2[r] = __uint_as_float(blo) + __uint_as_float(pblo)
                  + __uint_as_float(bhi) + __uint_as_float(pbhi);
        }

        if (wr) {
            if (t >= 1) {                      // h2_{t-1}
#pragma unroll
                for (int r = 0; r < 4; r++) {
                    hfin[r] = fmaxf(s2[r] + b2v, 0.f);
                    hn2[r * RSTR + physu] = hfin[r];
                }
            }
            if (t < T_) {                      // h1_t
#pragma unroll
                for (int r = 0; r < 4; r++) {
                    hn1[r * RSTR + physu] = fmaxf(s1[r] + pv[r], 0.f);
                    pv[r] = pn[r];
                }
            }
        }
        __syncthreads();
    }

    // final projection: writers hold h2_{T-1}(4 rows, unit u) in hfin
    if (wr) {
        float wd = Wdc[u];
        part_s[u] = make_float4(hfin[0] * wd, hfin[1] * wd, hfin[2] * wd, hfin[3] * wd);
    }
    __syncthreads();
    if (tid < 4) {
        float ssum = 0.f;
        for (int i = 0; i < U_; i++) ssum += ((const float*)(part_s + i))[tid];
        dout[r0 + tid] = ssum + bdc[0];
    }
}

// ============================================================================
extern "C" void kernel_launch(void* const* d_in, const int* in_sizes, int n_in,
                              void* d_out, int out_size)
{
    (void)in_sizes; (void)n_in; (void)out_size;
    const float* x   = (const float*)d_in[0];
    const float* Wx1 = (const float*)d_in[1];
    const float* Wh1 = (const float*)d_in[2];
    const float* b1  = (const float*)d_in[3];
    const float* Wx2 = (const float*)d_in[4];
    const float* Wh2 = (const float*)d_in[5];
    const float* b2  = (const float*)d_in[6];
    const float* Wd  = (const float*)d_in[7];
    const float* bd  = (const float*)d_in[8];
    float* out = (float*)d_out;

    float* pbuf;
    cudaGetSymbolAddress((void**)&pbuf, g_pbuf);

    const int ngrid = (T_ * B_) / 64;                        // 8192 tiles
    const int smemA = (64 * U_ + 64 * 68) * sizeof(float);   // 50176 B
    cudaFuncSetAttribute(gemm_bias<64, true>,
                         cudaFuncAttributeMaxDynamicSharedMemorySize, smemA);

    // Phase A: px1 = x @ Wx1 + b1           (layout [t][b][u])
    gemm_bias<64, true><<<ngrid, 256, smemA>>>(x, Wx1, b1, pbuf);
    // Phases B+C+D fully fused: both recurrences + output projection
    recurBCD<<<B_ / 4, 256>>>(pbuf, Wh1, Wx2, b2, Wh2, Wd, bd, out);
}